// round 13
// baseline (speedup 1.0000x reference)
#include <cuda_runtime.h>
#include <math.h>

#define NN   50000
#define E0   800000
#define ETOT 850000
#define F1   256          // heads*HID  (layer-1 concat width)
#define FZ   1024         // heads * 256 (aggregated-input width for layer 2)
#define NT   49           // scan tiles of 1024

// ---------------- scratch (device globals; no allocations) ----------------
__device__ float g_h1[(size_t)NN * F1];    // layer1 pre-attn features
__device__ float g_hr[(size_t)NN * F1];    // layer1 post-attn relu output
__device__ float g_z[(size_t)NN * FZ];     // layer2 aggregated inputs (1/(4D) folded)
__device__ float g_o[(size_t)NN * 128];    // layer2 GEMM output (pre-LN)
__device__ float g_es[NN * 4];             // e_src per node/head
__device__ float g_ed[NN * 4];             // e_dst per node/head
__device__ float g_va[4 * 256];            // W2 @ a_src2 per head
__device__ float g_vb[4 * 256];            // W2 @ a_dst2 per head
__device__ float g_w2p[FZ * 128];          // rearranged W2: [h*256+k][c] = W2[k][h*128+c]
__device__ int   g_deg[NN];
__device__ int   g_rowptr[NN + 1];
__device__ int   g_pos[NN];
__device__ int   g_srcs[ETOT];
__device__ int   g_part[64];
__device__ int   g_partoff[64];
__device__ int   g_is64;

// ---------------- dtype helpers ----------------
__device__ __forceinline__ void edge_nodes(const void* __restrict__ ei, int e,
                                           int& src, int& dst) {
    if (e >= E0) { src = dst = e - E0; return; }
    if (g_is64) {
        const long long* p = (const long long*)ei;
        src = (int)p[e];
        dst = (int)p[E0 + e];
    } else {
        const int* p = (const int*)ei;
        src = p[e];
        dst = p[E0 + e];
    }
}

__global__ void detect_idx_kernel(const int* __restrict__ ei32) {
    if (threadIdx.x == 0) {
        int all0 = 1;
        for (int i = 1; i < 256; i += 2) all0 &= (ei32[i] == 0);
        g_is64 = all0;
    }
}

// ---------------- CSR build ----------------
__global__ void zero_deg() {
    int i = blockIdx.x * blockDim.x + threadIdx.x;
    if (i < NN) g_deg[i] = 0;
}

__global__ void hist_kernel(const void* __restrict__ ei) {
    int e = blockIdx.x * blockDim.x + threadIdx.x;
    if (e >= ETOT) return;
    int src, dst;
    edge_nodes(ei, e, src, dst);
    atomicAdd(&g_deg[dst], 1);
}

__global__ void scan_tiles() {
    __shared__ int warpsum[32];
    int tid = threadIdx.x;
    int i = blockIdx.x * 1024 + tid;
    int lane = tid & 31, wid = tid >> 5;
    int v = (i < NN) ? g_deg[i] : 0;
    int s = v;
#pragma unroll
    for (int off = 1; off < 32; off <<= 1) {
        int t = __shfl_up_sync(0xffffffffu, s, off);
        if (lane >= off) s += t;
    }
    if (lane == 31) warpsum[wid] = s;
    __syncthreads();
    if (wid == 0) {
        int ws = warpsum[lane];
#pragma unroll
        for (int off = 1; off < 32; off <<= 1) {
            int t = __shfl_up_sync(0xffffffffu, ws, off);
            if (lane >= off) ws += t;
        }
        warpsum[lane] = ws;
    }
    __syncthreads();
    int excl = s - v + (wid > 0 ? warpsum[wid - 1] : 0);
    if (i < NN) g_rowptr[i] = excl;
    if (tid == 0) g_part[blockIdx.x] = warpsum[31];
}

__global__ void scan_parts() {
    __shared__ int sp[64];
    int tid = threadIdx.x;
    int v = (tid < NT) ? g_part[tid] : 0;
    sp[tid] = v;
    __syncthreads();
#pragma unroll
    for (int off = 1; off < 64; off <<= 1) {
        int t = sp[tid];
        int add = (tid >= off) ? sp[tid - off] : 0;
        __syncthreads();
        sp[tid] = t + add;
        __syncthreads();
    }
    g_partoff[tid] = sp[tid] - v;
}

__global__ void add_offsets() {
    int i = blockIdx.x * 1024 + threadIdx.x;
    if (i < NN) {
        int r = g_rowptr[i] + g_partoff[blockIdx.x];
        g_rowptr[i] = r;
        g_pos[i]    = r;
    }
    if (i == 0) g_rowptr[NN] = ETOT;
}

__global__ void scatter_kernel(const void* __restrict__ ei) {
    int e = blockIdx.x * blockDim.x + threadIdx.x;
    if (e >= ETOT) return;
    int src, dst;
    edge_nodes(ei, e, src, dst);
    int p = atomicAdd(&g_pos[dst], 1);
    g_srcs[p] = src;
}

// ---------------- layer-2 precompute ----------------
__global__ void build_w2p(const float* __restrict__ W2) {
    int i = blockIdx.x * blockDim.x + threadIdx.x;
    if (i >= FZ * 128) return;
    int r = i >> 7;            // h*256+k
    int c = i & 127;
    int h = r >> 8;
    int k = r & 255;
    g_w2p[i] = W2[k * 512 + h * 128 + c];
}

__global__ void build_va(const float* __restrict__ W2, const float* __restrict__ a_src,
                         const float* __restrict__ a_dst) {
    int i = threadIdx.x;       // 1024 = h*256+k
    int h = i >> 8;
    int k = i & 255;
    const float* wrow = W2 + k * 512 + h * 128;
    const float* as = a_src + h * 128;
    const float* ad = a_dst + h * 128;
    float sa = 0.f, sb = 0.f;
#pragma unroll 4
    for (int c = 0; c < 128; c++) {
        float w = wrow[c];
        sa += w * as[c];
        sb += w * ad[c];
    }
    g_va[i] = sa;
    g_vb[i] = sb;
}

// ---------------- tf32 GEMM, 128x128 tile, cp.async 2-stage (R12-proven) ----------
__device__ __forceinline__ unsigned f2tf32(float f) {
    unsigned r;
    asm("cvt.rna.tf32.f32 %0, %1;" : "=r"(r) : "f"(f));
    return r;
}
__device__ __forceinline__ void mma_tf32(float* d, const unsigned* a, const unsigned* b) {
    asm volatile(
        "mma.sync.aligned.m16n8k8.row.col.f32.tf32.tf32.f32 "
        "{%0,%1,%2,%3}, {%4,%5,%6,%7}, {%8,%9}, {%0,%1,%2,%3};"
        : "+f"(d[0]), "+f"(d[1]), "+f"(d[2]), "+f"(d[3])
        : "r"(a[0]), "r"(a[1]), "r"(a[2]), "r"(a[3]), "r"(b[0]), "r"(b[1]));
}
__device__ __forceinline__ void cp_async16(unsigned saddr, const void* gaddr, int srcb) {
    asm volatile("cp.async.ca.shared.global [%0], [%1], 16, %2;"
                 :: "r"(saddr), "l"(gaddr), "r"(srcb));
}

#define AS_STRIDE 36
#define BS_STRIDE 136
#define AS_ELEMS  (128 * AS_STRIDE)
#define BS_ELEMS  (32 * BS_STRIDE)
#define GEMM_SMEM ((2 * AS_ELEMS + 2 * BS_ELEMS) * 4)   // 71680 B

__global__ __launch_bounds__(256) void gemm_db(const float* __restrict__ A,
                                               const float* __restrict__ B,
                                               float* __restrict__ C,
                                               int n, int K, int J) {
    extern __shared__ float sm[];
    float* As = sm;
    float* Bs = sm + 2 * AS_ELEMS;
    int tid  = threadIdx.x;
    int warp = tid >> 5, lane = tid & 31;
    int wm = (warp & 3) * 32;
    int wn = (warp >> 2) * 64;
    int row0 = blockIdx.y * 128;
    int col0 = blockIdx.x * 128;
    int lr = lane >> 2, lc = lane & 3;

    unsigned as_base = (unsigned)__cvta_generic_to_shared(As);
    unsigned bs_base = (unsigned)__cvta_generic_to_shared(Bs);

    float acc[2][8][4];
#pragma unroll
    for (int i = 0; i < 2; i++)
#pragma unroll
        for (int j = 0; j < 8; j++)
#pragma unroll
            for (int q = 0; q < 4; q++) acc[i][j][q] = 0.f;

    auto issue = [&](int st, int k0) {
#pragma unroll
        for (int q = 0; q < 4; q++) {
            int c = tid + q * 256;
            int ar = c >> 3, kc = (c & 7) * 4;
            int grow = row0 + ar;
            unsigned dst = as_base + (st * AS_ELEMS + ar * AS_STRIDE + kc) * 4;
            const float* src = A + (size_t)grow * K + k0 + kc;
            cp_async16(dst, src, (grow < n) ? 16 : 0);
        }
#pragma unroll
        for (int q = 0; q < 4; q++) {
            int c = tid + q * 256;
            int br = c >> 5, bc = (c & 31) * 4;
            unsigned dst = bs_base + (st * BS_ELEMS + br * BS_STRIDE + bc) * 4;
            const float* src = B + (size_t)(k0 + br) * J + col0 + bc;
            cp_async16(dst, src, 16);
        }
        asm volatile("cp.async.commit_group;");
    };

    issue(0, 0);
    int st = 0;
    for (int k0 = 0; k0 < K; k0 += 32, st ^= 1) {
        if (k0 + 32 < K) {
            issue(st ^ 1, k0 + 32);
            asm volatile("cp.async.wait_group 1;");
        } else {
            asm volatile("cp.async.wait_group 0;");
        }
        __syncthreads();
        const float* as = As + st * AS_ELEMS;
        const float* bs = Bs + st * BS_ELEMS;
#pragma unroll
        for (int kk = 0; kk < 32; kk += 8) {
            unsigned a[2][4], b[8][2];
#pragma unroll
            for (int mf = 0; mf < 2; mf++) {
                int r = wm + mf * 16 + lr;
                a[mf][0] = f2tf32(as[r * AS_STRIDE + kk + lc]);
                a[mf][1] = f2tf32(as[(r + 8) * AS_STRIDE + kk + lc]);
                a[mf][2] = f2tf32(as[r * AS_STRIDE + kk + lc + 4]);
                a[mf][3] = f2tf32(as[(r + 8) * AS_STRIDE + kk + lc + 4]);
            }
#pragma unroll
            for (int nf = 0; nf < 8; nf++) {
                int c = wn + nf * 8 + lr;
                b[nf][0] = f2tf32(bs[(kk + lc) * BS_STRIDE + c]);
                b[nf][1] = f2tf32(bs[(kk + lc + 4) * BS_STRIDE + c]);
            }
#pragma unroll
            for (int mf = 0; mf < 2; mf++)
#pragma unroll
                for (int nf = 0; nf < 8; nf++)
                    mma_tf32(acc[mf][nf], a[mf], b[nf]);
        }
        __syncthreads();
    }
#pragma unroll
    for (int mf = 0; mf < 2; mf++) {
#pragma unroll
        for (int nf = 0; nf < 8; nf++) {
            int r = row0 + wm + mf * 16 + lr;
            int c = col0 + wn + nf * 8 + 2 * lc;
            if (r < n) {
                C[(size_t)r * J + c]     = acc[mf][nf][0];
                C[(size_t)r * J + c + 1] = acc[mf][nf][1];
            }
            if (r + 8 < n) {
                C[(size_t)(r + 8) * J + c]     = acc[mf][nf][2];
                C[(size_t)(r + 8) * J + c + 1] = acc[mf][nf][3];
            }
        }
    }
}

// ---------------- layer-1 attention scores ----------------
template <int C>
__global__ void attn_scores(const float* __restrict__ h, const float* __restrict__ a_src,
                            const float* __restrict__ a_dst, float* __restrict__ es,
                            float* __restrict__ ed) {
    int warp = (blockIdx.x * blockDim.x + threadIdx.x) >> 5;
    int lane = threadIdx.x & 31;
    if (warp >= NN) return;
    const float4* hr  = reinterpret_cast<const float4*>(h + (size_t)warp * 4 * C);
    const float4* as4 = reinterpret_cast<const float4*>(a_src);
    const float4* ad4 = reinterpret_cast<const float4*>(a_dst);
    constexpr int Q = C / 32;
    float ss = 0.f, sd = 0.f;
#pragma unroll
    for (int q = 0; q < Q; q++) {
        int idx = lane * Q + q;
        float4 hv = hr[idx];
        float4 av = as4[idx];
        float4 dv = ad4[idx];
        ss += hv.x * av.x + hv.y * av.y + hv.z * av.z + hv.w * av.w;
        sd += hv.x * dv.x + hv.y * dv.y + hv.z * dv.z + hv.w * dv.w;
    }
#pragma unroll
    for (int off = 4; off >= 1; off >>= 1) {
        ss += __shfl_down_sync(0xffffffffu, ss, off);
        sd += __shfl_down_sync(0xffffffffu, sd, off);
    }
    if ((lane & 7) == 0) {
        int head = lane >> 3;
        es[warp * 4 + head] = ss;
        ed[warp * 4 + head] = sd;
    }
}

// ---------------- layer-2 scores: es2[n,h] = hr[n]·va[h] (256-dim) ----------------
__global__ void attn2_scores(const float* __restrict__ hr, float* __restrict__ es,
                             float* __restrict__ ed) {
    int warp = (blockIdx.x * blockDim.x + threadIdx.x) >> 5;
    int lane = threadIdx.x & 31;
    if (warp >= NN) return;
    int head = lane >> 3, w8 = lane & 7;
    const float4* hrow = reinterpret_cast<const float4*>(hr + (size_t)warp * F1);
    const float4* va = reinterpret_cast<const float4*>(g_va + head * 256);
    const float4* vb = reinterpret_cast<const float4*>(g_vb + head * 256);
    float ss = 0.f, sd = 0.f;
#pragma unroll
    for (int q = 0; q < 8; q++) {
        int idx = w8 * 8 + q;
        float4 hv = hrow[idx];
        float4 av = va[idx];
        float4 dv = vb[idx];
        ss += hv.x * av.x + hv.y * av.y + hv.z * av.z + hv.w * av.w;
        sd += hv.x * dv.x + hv.y * dv.y + hv.z * dv.z + hv.w * dv.w;
    }
#pragma unroll
    for (int off = 4; off >= 1; off >>= 1) {
        ss += __shfl_down_sync(0xffffffffu, ss, off);
        sd += __shfl_down_sync(0xffffffffu, sd, off);
    }
    if (w8 == 0) {
        es[warp * 4 + head] = ss;
        ed[warp * 4 + head] = sd;
    }
}

// ---------------- fused per-node GAT aggregation ----------------
__device__ __forceinline__ float4 expleaky4(float4 a, float4 b) {
    float4 v;
    v.x = a.x + b.x; v.x = v.x > 0.f ? v.x : 0.2f * v.x; v.x = __expf(v.x);
    v.y = a.y + b.y; v.y = v.y > 0.f ? v.y : 0.2f * v.y; v.y = __expf(v.y);
    v.z = a.z + b.z; v.z = v.z > 0.f ? v.z : 0.2f * v.z; v.z = __expf(v.z);
    v.w = a.w + b.w; v.w = v.w > 0.f ? v.w : 0.2f * v.w; v.w = __expf(v.w);
    return v;
}

#define CHUNK 64

// Layer 1 (R11/R12-proven): softmax weights + accumulate + bias + relu.
__global__ __launch_bounds__(128) void gat_agg1(
    const float* __restrict__ h, const float* __restrict__ es, const float* __restrict__ ed,
    const float* __restrict__ bias, float* __restrict__ out) {
    int n = blockIdx.x;
    int tid = threadIdx.x;
    int lane = tid & 31, wid = tid >> 5;
    int r0 = g_rowptr[n], r1 = g_rowptr[n + 1];
    int deg = r1 - r0;
    float4 edv = *reinterpret_cast<const float4*>(ed + n * 4);

    __shared__ float4 s_red[4];
    __shared__ int    s_src[CHUNK];
    __shared__ float4 s_w[CHUNK];

    const float* hp = h + tid * 2;

    float a0 = 0.f, a1 = 0.f;
    float4 dpart = make_float4(0.f, 0.f, 0.f, 0.f);
    for (int base = 0; base < deg; base += CHUNK) {
        int cn = deg - base; if (cn > CHUNK) cn = CHUNK;
        if (tid < cn) {
            int s = g_srcs[r0 + base + tid];
            float4 w = expleaky4(*reinterpret_cast<const float4*>(es + s * 4), edv);
            s_src[tid] = s;
            s_w[tid] = w;
            dpart.x += w.x; dpart.y += w.y; dpart.z += w.z; dpart.w += w.w;
        }
        __syncthreads();
        const float* wf = reinterpret_cast<const float*>(s_w);
        int j = 0;
        for (; j + 4 <= cn; j += 4) {
            int s0 = s_src[j + 0], s1 = s_src[j + 1];
            int s2 = s_src[j + 2], s3 = s_src[j + 3];
            float w0 = wf[(j + 0) * 4 + wid];
            float w1 = wf[(j + 1) * 4 + wid];
            float w2 = wf[(j + 2) * 4 + wid];
            float w3 = wf[(j + 3) * 4 + wid];
            float2 v0 = *reinterpret_cast<const float2*>(hp + (size_t)s0 * F1);
            float2 v1 = *reinterpret_cast<const float2*>(hp + (size_t)s1 * F1);
            float2 v2 = *reinterpret_cast<const float2*>(hp + (size_t)s2 * F1);
            float2 v3 = *reinterpret_cast<const float2*>(hp + (size_t)s3 * F1);
            a0 += w0 * v0.x; a1 += w0 * v0.y;
            a0 += w1 * v1.x; a1 += w1 * v1.y;
            a0 += w2 * v2.x; a1 += w2 * v2.y;
            a0 += w3 * v3.x; a1 += w3 * v3.y;
        }
        for (; j < cn; j++) {
            int s = s_src[j];
            float w = wf[j * 4 + wid];
            float2 hv = *reinterpret_cast<const float2*>(hp + (size_t)s * F1);
            a0 += w * hv.x;
            a1 += w * hv.y;
        }
        __syncthreads();
    }
#pragma unroll
    for (int off = 16; off >= 1; off >>= 1) {
        dpart.x += __shfl_xor_sync(0xffffffffu, dpart.x, off);
        dpart.y += __shfl_xor_sync(0xffffffffu, dpart.y, off);
        dpart.z += __shfl_xor_sync(0xffffffffu, dpart.z, off);
        dpart.w += __shfl_xor_sync(0xffffffffu, dpart.w, off);
    }
    if (lane == 0) s_red[wid] = dpart;
    __syncthreads();
    float4 dt = s_red[0];
    dt.x += s_red[1].x + s_red[2].x + s_red[3].x;
    dt.y += s_red[1].y + s_red[2].y + s_red[3].y;
    dt.z += s_red[1].z + s_red[2].z + s_red[3].z;
    dt.w += s_red[1].w + s_red[2].w + s_red[3].w;
    float den = ((const float*)&dt)[wid] + 1e-16f;
    float inv = 1.f / den;
    int c = tid * 2;
    float o0 = a0 * inv + bias[c];
    float o1 = a1 * inv + bias[c + 1];
    o0 = o0 > 0.f ? o0 : 0.f;
    o1 = o1 > 0.f ? o1 : 0.f;
    *reinterpret_cast<float2*>(out + (size_t)n * F1 + c) = make_float2(o0, o1);
}

// Layer 2: aggregate hr (256-dim) with all 4 head weights -> z[n, h*256+k],
// 1/(4*D_h) folded. Gathers 1KB/edge. 4-deep pipelined.
__global__ __launch_bounds__(128) void gat_agg2z(
    const float* __restrict__ hr, const float* __restrict__ es,
    const float* __restrict__ ed, float* __restrict__ z) {
    int n = blockIdx.x;
    int tid = threadIdx.x;
    int lane = tid & 31, wid = tid >> 5;
    int r0 = g_rowptr[n], r1 = g_rowptr[n + 1];
    int deg = r1 - r0;
    float4 edv = *reinterpret_cast<const float4*>(ed + n * 4);

    __shared__ float4 s_red[4];
    __shared__ int    s_src[CHUNK];
    __shared__ float4 s_w[CHUNK];

    const float* hp = hr + tid * 2;

    float2 az[4] = {{0.f,0.f},{0.f,0.f},{0.f,0.f},{0.f,0.f}};
    float4 dpart = make_float4(0.f, 0.f, 0.f, 0.f);
    for (int base = 0; base < deg; base += CHUNK) {
        int cn = deg - base; if (cn > CHUNK) cn = CHUNK;
        if (tid < cn) {
            int s = g_srcs[r0 + base + tid];
            float4 w = expleaky4(*reinterpret_cast<const float4*>(es + s * 4), edv);
            s_src[tid] = s;
            s_w[tid] = w;
            dpart.x += w.x; dpart.y += w.y; dpart.z += w.z; dpart.w += w.w;
        }
        __syncthreads();
        int j = 0;
        for (; j + 2 <= cn; j += 2) {
            int s0 = s_src[j + 0], s1 = s_src[j + 1];
            float4 w0 = s_w[j + 0];
            float4 w1 = s_w[j + 1];
            float2 v0 = *reinterpret_cast<const float2*>(hp + (size_t)s0 * F1);
            float2 v1 = *reinterpret_cast<const float2*>(hp + (size_t)s1 * F1);
            az[0].x += w0.x * v0.x; az[0].y += w0.x * v0.y;
            az[1].x += w0.y * v0.x; az[1].y += w0.y * v0.y;
            az[2].x += w0.z * v0.x; az[2].y += w0.z * v0.y;
            az[3].x += w0.w * v0.x; az[3].y += w0.w * v0.y;
            az[0].x += w1.x * v1.x; az[0].y += w1.x * v1.y;
            az[1].x += w1.y * v1.x; az[1].y += w1.y * v1.y;
            az[2].x += w1.z * v1.x; az[2].y += w1.z * v1.y;
            az[3].x += w1.w * v1.x; az[3].y += w1.w * v1.y;
        }
        for (; j < cn; j++) {
            int s = s_src[j];
            float4 w = s_w[j];
            float2 v = *reinterpret_cast<const float2*>(hp + (size_t)s * F1);
            az[0].x += w.x * v.x; az[0].y += w.x * v.y;
            az[1].x += w.y * v.x; az[1].y += w.y * v.y;
            az[2].x += w.z * v.x; az[2].y += w.z * v.y;
            az[3].x += w.w * v.x; az[3].y += w.w * v.y;
        }
        __syncthreads();
    }
#pragma unroll
    for (int off = 16; off >= 1; off >>= 1) {
        dpart.x += __shfl_xor_sync(0xffffffffu, dpart.x, off);
        dpart.y += __shfl_xor_sync(0xffffffffu, dpart.y, off);
        dpart.z += __shfl_xor_sync(0xffffffffu, dpart.z, off);
        dpart.w += __shfl_xor_sync(0xffffffffu, dpart.w, off);
    }
    if (lane == 0) s_red[wid] = dpart;
    __syncthreads();
    float4 dt = s_red[0];
    dt.x += s_red[1].x + s_red[2].x + s_red[3].x;
    dt.y += s_red[1].y + s_red[2].y + s_red[3].y;
    dt.z += s_red[1].z + s_red[2].z + s_red[3].z;
    dt.w += s_red[1].w + s_red[2].w + s_red[3].w;
    float iv0 = 0.25f / (dt.x + 1e-16f);
    float iv1 = 0.25f / (dt.y + 1e-16f);
    float iv2 = 0.25f / (dt.z + 1e-16f);
    float iv3 = 0.25f / (dt.w + 1e-16f);
    float* zr = z + (size_t)n * FZ + tid * 2;
    *reinterpret_cast<float2*>(zr + 0 * 256) = make_float2(az[0].x * iv0, az[0].y * iv0);
    *reinterpret_cast<float2*>(zr + 1 * 256) = make_float2(az[1].x * iv1, az[1].y * iv1);
    *reinterpret_cast<float2*>(zr + 2 * 256) = make_float2(az[2].x * iv2, az[2].y * iv2);
    *reinterpret_cast<float2*>(zr + 3 * 256) = make_float2(az[3].x * iv3, az[3].y * iv3);
}

// ---------------- final: bias + LayerNorm over 128 channels ----------------
__global__ __launch_bounds__(128) void ln_final(
    const float* __restrict__ go, const float* __restrict__ b2,
    const float* __restrict__ gamma, const float* __restrict__ beta,
    float* __restrict__ out) {
    int n = blockIdx.x;
    int c = threadIdx.x;
    int lane = c & 31, wid = c >> 5;
    __shared__ float s_ln[4];
    float y = go[(size_t)n * 128 + c] + b2[c];
    float t = y;
#pragma unroll
    for (int off = 16; off >= 1; off >>= 1) t += __shfl_xor_sync(0xffffffffu, t, off);
    if (lane == 0) s_ln[wid] = t;
    __syncthreads();
    float mu = (s_ln[0] + s_ln[1] + s_ln[2] + s_ln[3]) * (1.f / 128.f);
    float dv = y - mu;
    t = dv * dv;
#pragma unroll
    for (int off = 16; off >= 1; off >>= 1) t += __shfl_xor_sync(0xffffffffu, t, off);
    __syncthreads();
    if (lane == 0) s_ln[wid] = t;
    __syncthreads();
    float var = (s_ln[0] + s_ln[1] + s_ln[2] + s_ln[3]) * (1.f / 128.f);
    out[(size_t)n * 128 + c] = dv * rsqrtf(var + 1e-5f) * gamma[c] + beta[c];
}

// ---------------- launch ----------------
extern "C" void kernel_launch(void* const* d_in, const int* in_sizes, int n_in,
                              void* d_out, int out_size) {
    const float* x     = (const float*)d_in[0];
    const void*  ei    = d_in[1];
    const float* W1    = (const float*)d_in[2];
    const float* as1   = (const float*)d_in[3];
    const float* ad1   = (const float*)d_in[4];
    const float* b1    = (const float*)d_in[5];
    const float* W2    = (const float*)d_in[6];
    const float* as2   = (const float*)d_in[7];
    const float* ad2   = (const float*)d_in[8];
    const float* b2    = (const float*)d_in[9];
    const float* gamma = (const float*)d_in[10];
    const float* beta  = (const float*)d_in[11];
    float*       out   = (float*)d_out;

    float *p_h1, *p_hr, *p_z, *p_o, *p_es, *p_ed, *p_w2p;
    cudaGetSymbolAddress((void**)&p_h1,  g_h1);
    cudaGetSymbolAddress((void**)&p_hr,  g_hr);
    cudaGetSymbolAddress((void**)&p_z,   g_z);
    cudaGetSymbolAddress((void**)&p_o,   g_o);
    cudaGetSymbolAddress((void**)&p_es,  g_es);
    cudaGetSymbolAddress((void**)&p_ed,  g_ed);
    cudaGetSymbolAddress((void**)&p_w2p, g_w2p);

    cudaFuncSetAttribute(gemm_db, cudaFuncAttributeMaxDynamicSharedMemorySize, GEMM_SMEM);

    const int TB = 256;
    int rows128 = (NN + 127) / 128;             // 391
    int nodeWarpBlocks = (NN + 7) / 8;          // 6250
    int edgeBlocks = (ETOT + TB - 1) / TB;      // 3321

    // ---- CSR build + layer-2 precompute ----
    detect_idx_kernel<<<1, 32>>>((const int*)ei);
    zero_deg<<<(NN + TB - 1) / TB, TB>>>();
    hist_kernel<<<edgeBlocks, TB>>>(ei);
    scan_tiles<<<NT, 1024>>>();
    scan_parts<<<1, 64>>>();
    add_offsets<<<NT, 1024>>>();
    scatter_kernel<<<edgeBlocks, TB>>>(ei);
    build_w2p<<<(FZ * 128 + 255) / 256, 256>>>(W2);
    build_va<<<1, 1024>>>(W2, as2, ad2);

    // ---- layer 1 ----
    gemm_db<<<dim3(F1 / 128, rows128), 256, GEMM_SMEM>>>(x, W1, p_h1, NN, 128, F1);
    attn_scores<64><<<nodeWarpBlocks, TB>>>(p_h1, as1, ad1, p_es, p_ed);
    gat_agg1<<<NN, 128>>>(p_h1, p_es, p_ed, b1, p_hr);

    // ---- layer 2 (aggregate-then-transform) ----
    attn2_scores<<<nodeWarpBlocks, TB>>>(p_hr, p_es, p_ed);
    gat_agg2z<<<NN, 128>>>(p_hr, p_es, p_ed, p_z);
    gemm_db<<<dim3(1, rows128), 256, GEMM_SMEM>>>(p_z, p_w2p, p_o, NN, FZ, 128);
    ln_final<<<NN, 128>>>(p_o, b2, gamma, beta, out);
}

// round 14
// speedup vs baseline: 1.4332x; 1.4332x over previous
#include <cuda_runtime.h>
#include <math.h>

#define NN   50000
#define E0   800000
#define ETOT 850000
#define F1   256          // heads*HID  (layer-1 concat width)
#define F2   512          // heads*OUT  (layer-2 pre-mean width)
#define NT   49           // scan tiles of 1024

// ---------------- scratch (device globals; no allocations) ----------------
__device__ float g_h1[(size_t)NN * F1];    // layer1 pre-attn features
__device__ float g_hr[(size_t)NN * F1];    // layer1 post-attn relu output (GEMM2 input)
__device__ float g_h2[(size_t)NN * F2];    // layer2 pre-attn features
__device__ float g_es[NN * 4];             // e_src per node/head
__device__ float g_ed[NN * 4];             // e_dst per node/head
__device__ int   g_deg[NN];
__device__ int   g_rowptr[NN + 1];
__device__ int   g_pos[NN];
__device__ int   g_srcs[ETOT];
__device__ int   g_part[64];
__device__ int   g_partoff[64];
__device__ int   g_is64;

// ---------------- dtype helpers ----------------
__device__ __forceinline__ void edge_nodes(const void* __restrict__ ei, int e,
                                           int& src, int& dst) {
    if (e >= E0) { src = dst = e - E0; return; }
    if (g_is64) {
        const long long* p = (const long long*)ei;
        src = (int)p[e];
        dst = (int)p[E0 + e];
    } else {
        const int* p = (const int*)ei;
        src = p[e];
        dst = p[E0 + e];
    }
}

__global__ void detect_idx_kernel(const int* __restrict__ ei32) {
    if (threadIdx.x == 0) {
        int all0 = 1;
        for (int i = 1; i < 256; i += 2) all0 &= (ei32[i] == 0);
        g_is64 = all0;
    }
}

// ---------------- CSR build ----------------
__global__ void zero_deg() {
    int i = blockIdx.x * blockDim.x + threadIdx.x;
    if (i < NN) g_deg[i] = 0;
}

__global__ void hist_kernel(const void* __restrict__ ei) {
    int e = blockIdx.x * blockDim.x + threadIdx.x;
    if (e >= ETOT) return;
    int src, dst;
    edge_nodes(ei, e, src, dst);
    atomicAdd(&g_deg[dst], 1);
}

__global__ void scan_tiles() {
    __shared__ int warpsum[32];
    int tid = threadIdx.x;
    int i = blockIdx.x * 1024 + tid;
    int lane = tid & 31, wid = tid >> 5;
    int v = (i < NN) ? g_deg[i] : 0;
    int s = v;
#pragma unroll
    for (int off = 1; off < 32; off <<= 1) {
        int t = __shfl_up_sync(0xffffffffu, s, off);
        if (lane >= off) s += t;
    }
    if (lane == 31) warpsum[wid] = s;
    __syncthreads();
    if (wid == 0) {
        int ws = warpsum[lane];
#pragma unroll
        for (int off = 1; off < 32; off <<= 1) {
            int t = __shfl_up_sync(0xffffffffu, ws, off);
            if (lane >= off) ws += t;
        }
        warpsum[lane] = ws;
    }
    __syncthreads();
    int excl = s - v + (wid > 0 ? warpsum[wid - 1] : 0);
    if (i < NN) g_rowptr[i] = excl;
    if (tid == 0) g_part[blockIdx.x] = warpsum[31];
}

__global__ void scan_parts() {
    __shared__ int sp[64];
    int tid = threadIdx.x;
    int v = (tid < NT) ? g_part[tid] : 0;
    sp[tid] = v;
    __syncthreads();
#pragma unroll
    for (int off = 1; off < 64; off <<= 1) {
        int t = sp[tid];
        int add = (tid >= off) ? sp[tid - off] : 0;
        __syncthreads();
        sp[tid] = t + add;
        __syncthreads();
    }
    g_partoff[tid] = sp[tid] - v;
}

__global__ void add_offsets() {
    int i = blockIdx.x * 1024 + threadIdx.x;
    if (i < NN) {
        int r = g_rowptr[i] + g_partoff[blockIdx.x];
        g_rowptr[i] = r;
        g_pos[i]    = r;
    }
    if (i == 0) g_rowptr[NN] = ETOT;
}

__global__ void scatter_kernel(const void* __restrict__ ei) {
    int e = blockIdx.x * blockDim.x + threadIdx.x;
    if (e >= ETOT) return;
    int src, dst;
    edge_nodes(ei, e, src, dst);
    int p = atomicAdd(&g_pos[dst], 1);
    g_srcs[p] = src;
}

// ---------------- tf32 GEMM, 128x128 tile, cp.async 2-stage, fused attn scores ----
__device__ __forceinline__ unsigned f2tf32(float f) {
    unsigned r;
    asm("cvt.rna.tf32.f32 %0, %1;" : "=r"(r) : "f"(f));
    return r;
}
__device__ __forceinline__ void mma_tf32(float* d, const unsigned* a, const unsigned* b) {
    asm volatile(
        "mma.sync.aligned.m16n8k8.row.col.f32.tf32.tf32.f32 "
        "{%0,%1,%2,%3}, {%4,%5,%6,%7}, {%8,%9}, {%0,%1,%2,%3};"
        : "+f"(d[0]), "+f"(d[1]), "+f"(d[2]), "+f"(d[3])
        : "r"(a[0]), "r"(a[1]), "r"(a[2]), "r"(a[3]), "r"(b[0]), "r"(b[1]));
}
__device__ __forceinline__ void cp_async16(unsigned saddr, const void* gaddr, int srcb) {
    asm volatile("cp.async.ca.shared.global [%0], [%1], 16, %2;"
                 :: "r"(saddr), "l"(gaddr), "r"(srcb));
}

#define AS_STRIDE 36
#define BS_STRIDE 136
#define AS_ELEMS  (128 * AS_STRIDE)
#define BS_ELEMS  (32 * BS_STRIDE)
#define GEMM_SMEM ((2 * AS_ELEMS + 2 * BS_ELEMS) * 4)   // 71680 B

// CH = per-head channel count for fused attention scores (0 = no fusion).
// Block columns [col0, col0+128) must align to head boundaries (true for CH=64,128).
template <int CH>
__global__ __launch_bounds__(256) void gemm_db(const float* __restrict__ A,
                                               const float* __restrict__ B,
                                               float* __restrict__ C,
                                               int n, int K, int J,
                                               const float* __restrict__ a_src,
                                               const float* __restrict__ a_dst,
                                               float* __restrict__ es,
                                               float* __restrict__ ed) {
    extern __shared__ float sm[];
    float* As = sm;
    float* Bs = sm + 2 * AS_ELEMS;
    int tid  = threadIdx.x;
    int warp = tid >> 5, lane = tid & 31;
    int wm = (warp & 3) * 32;
    int wn = (warp >> 2) * 64;
    int row0 = blockIdx.y * 128;
    int col0 = blockIdx.x * 128;
    int lr = lane >> 2, lc = lane & 3;

    unsigned as_base = (unsigned)__cvta_generic_to_shared(As);
    unsigned bs_base = (unsigned)__cvta_generic_to_shared(Bs);

    float acc[2][8][4];
#pragma unroll
    for (int i = 0; i < 2; i++)
#pragma unroll
        for (int j = 0; j < 8; j++)
#pragma unroll
            for (int q = 0; q < 4; q++) acc[i][j][q] = 0.f;

    auto issue = [&](int st, int k0) {
#pragma unroll
        for (int q = 0; q < 4; q++) {
            int c = tid + q * 256;
            int ar = c >> 3, kc = (c & 7) * 4;
            int grow = row0 + ar;
            unsigned dst = as_base + (st * AS_ELEMS + ar * AS_STRIDE + kc) * 4;
            const float* src = A + (size_t)grow * K + k0 + kc;
            cp_async16(dst, src, (grow < n) ? 16 : 0);
        }
#pragma unroll
        for (int q = 0; q < 4; q++) {
            int c = tid + q * 256;
            int br = c >> 5, bc = (c & 31) * 4;
            unsigned dst = bs_base + (st * BS_ELEMS + br * BS_STRIDE + bc) * 4;
            const float* src = B + (size_t)(k0 + br) * J + col0 + bc;
            cp_async16(dst, src, 16);
        }
        asm volatile("cp.async.commit_group;");
    };

    issue(0, 0);
    int st = 0;
    for (int k0 = 0; k0 < K; k0 += 32, st ^= 1) {
        if (k0 + 32 < K) {
            issue(st ^ 1, k0 + 32);
            asm volatile("cp.async.wait_group 1;");
        } else {
            asm volatile("cp.async.wait_group 0;");
        }
        __syncthreads();
        const float* as = As + st * AS_ELEMS;
        const float* bs = Bs + st * BS_ELEMS;
#pragma unroll
        for (int kk = 0; kk < 32; kk += 8) {
            unsigned a[2][4], b[8][2];
#pragma unroll
            for (int mf = 0; mf < 2; mf++) {
                int r = wm + mf * 16 + lr;
                a[mf][0] = f2tf32(as[r * AS_STRIDE + kk + lc]);
                a[mf][1] = f2tf32(as[(r + 8) * AS_STRIDE + kk + lc]);
                a[mf][2] = f2tf32(as[r * AS_STRIDE + kk + lc + 4]);
                a[mf][3] = f2tf32(as[(r + 8) * AS_STRIDE + kk + lc + 4]);
            }
#pragma unroll
            for (int nf = 0; nf < 8; nf++) {
                int c = wn + nf * 8 + lr;
                b[nf][0] = f2tf32(bs[(kk + lc) * BS_STRIDE + c]);
                b[nf][1] = f2tf32(bs[(kk + lc + 4) * BS_STRIDE + c]);
            }
#pragma unroll
            for (int mf = 0; mf < 2; mf++)
#pragma unroll
                for (int nf = 0; nf < 8; nf++)
                    mma_tf32(acc[mf][nf], a[mf], b[nf]);
        }
        __syncthreads();
    }

    // ---- store C ----
#pragma unroll
    for (int mf = 0; mf < 2; mf++) {
#pragma unroll
        for (int nf = 0; nf < 8; nf++) {
            int r = row0 + wm + mf * 16 + lr;
            int c = col0 + wn + nf * 8 + 2 * lc;
            if (r < n) {
                C[(size_t)r * J + c]     = acc[mf][nf][0];
                C[(size_t)r * J + c + 1] = acc[mf][nf][1];
            }
            if (r + 8 < n) {
                C[(size_t)(r + 8) * J + c]     = acc[mf][nf][2];
                C[(size_t)(r + 8) * J + c + 1] = acc[mf][nf][3];
            }
        }
    }

    // ---- fused attention scores from accumulators ----
    if (CH > 0) {
        // this n-warp's 64 columns lie within one head
        int head0 = (col0 + wn) / CH;
        float psrc[4] = {0.f, 0.f, 0.f, 0.f};   // rows: wm+lr, wm+lr+8, wm+16+lr, wm+16+lr+8
        float pdst[4] = {0.f, 0.f, 0.f, 0.f};
#pragma unroll
        for (int nf = 0; nf < 8; nf++) {
            int cin = (col0 + wn + nf * 8 + 2 * lc) % CH;
            float a0s = a_src[head0 * CH + cin], a1s = a_src[head0 * CH + cin + 1];
            float a0d = a_dst[head0 * CH + cin], a1d = a_dst[head0 * CH + cin + 1];
#pragma unroll
            for (int mf = 0; mf < 2; mf++) {
                psrc[mf * 2 + 0] += acc[mf][nf][0] * a0s + acc[mf][nf][1] * a1s;
                pdst[mf * 2 + 0] += acc[mf][nf][0] * a0d + acc[mf][nf][1] * a1d;
                psrc[mf * 2 + 1] += acc[mf][nf][2] * a0s + acc[mf][nf][3] * a1s;
                pdst[mf * 2 + 1] += acc[mf][nf][2] * a0d + acc[mf][nf][3] * a1d;
            }
        }
        // reduce over the 4 lc-lanes (lane = lr*4 + lc)
#pragma unroll
        for (int off = 1; off <= 2; off <<= 1) {
#pragma unroll
            for (int i = 0; i < 4; i++) {
                psrc[i] += __shfl_down_sync(0xffffffffu, psrc[i], off);
                pdst[i] += __shfl_down_sync(0xffffffffu, pdst[i], off);
            }
        }
        // part[row][nwarp][src/dst], 128*2*2 floats, reuse smem (mainloop done)
        float* part = sm;
        if (lc == 0) {
            int nw = warp >> 2;
#pragma unroll
            for (int i = 0; i < 4; i++) {
                int row = wm + (i >> 1) * 16 + lr + (i & 1) * 8;
                part[(row * 2 + nw) * 2 + 0] = psrc[i];
                part[(row * 2 + nw) * 2 + 1] = pdst[i];
            }
        }
        __syncthreads();
        if (tid < 128) {
            int grow = row0 + tid;
            if (grow < n) {
                if (CH == 64) {
                    int h0 = col0 / 64;   // n-warp0 -> h0, n-warp1 -> h0+1
                    es[grow * 4 + h0]     = part[(tid * 2 + 0) * 2 + 0];
                    ed[grow * 4 + h0]     = part[(tid * 2 + 0) * 2 + 1];
                    es[grow * 4 + h0 + 1] = part[(tid * 2 + 1) * 2 + 0];
                    ed[grow * 4 + h0 + 1] = part[(tid * 2 + 1) * 2 + 1];
                } else {                  // CH == 128: both n-warps same head
                    int h = col0 / 128;
                    es[grow * 4 + h] = part[(tid * 2 + 0) * 2 + 0] + part[(tid * 2 + 1) * 2 + 0];
                    ed[grow * 4 + h] = part[(tid * 2 + 0) * 2 + 1] + part[(tid * 2 + 1) * 2 + 1];
                }
            }
        }
    }
}

// ---------------- fused per-node GAT aggregation (R12-identical) ----------------
__device__ __forceinline__ float4 expleaky4(float4 a, float4 b) {
    float4 v;
    v.x = a.x + b.x; v.x = v.x > 0.f ? v.x : 0.2f * v.x; v.x = __expf(v.x);
    v.y = a.y + b.y; v.y = v.y > 0.f ? v.y : 0.2f * v.y; v.y = __expf(v.y);
    v.z = a.z + b.z; v.z = v.z > 0.f ? v.z : 0.2f * v.z; v.z = __expf(v.z);
    v.w = a.w + b.w; v.w = v.w > 0.f ? v.w : 0.2f * v.w; v.w = __expf(v.w);
    return v;
}

#define CHUNK 64

__global__ __launch_bounds__(128) void gat_agg1(
    const float* __restrict__ h, const float* __restrict__ es, const float* __restrict__ ed,
    const float* __restrict__ bias, float* __restrict__ out) {
    int n = blockIdx.x;
    int tid = threadIdx.x;
    int lane = tid & 31, wid = tid >> 5;
    int r0 = g_rowptr[n], r1 = g_rowptr[n + 1];
    int deg = r1 - r0;
    float4 edv = *reinterpret_cast<const float4*>(ed + n * 4);

    __shared__ float4 s_red[4];
    __shared__ int    s_src[CHUNK];
    __shared__ float4 s_w[CHUNK];

    const float* hp = h + tid * 2;

    float a0 = 0.f, a1 = 0.f;
    float4 dpart = make_float4(0.f, 0.f, 0.f, 0.f);
    for (int base = 0; base < deg; base += CHUNK) {
        int cn = deg - base; if (cn > CHUNK) cn = CHUNK;
        if (tid < cn) {
            int s = g_srcs[r0 + base + tid];
            float4 w = expleaky4(*reinterpret_cast<const float4*>(es + s * 4), edv);
            s_src[tid] = s;
            s_w[tid] = w;
            dpart.x += w.x; dpart.y += w.y; dpart.z += w.z; dpart.w += w.w;
        }
        __syncthreads();
        const float* wf = reinterpret_cast<const float*>(s_w);
        int j = 0;
        for (; j + 4 <= cn; j += 4) {
            int s0 = s_src[j + 0], s1 = s_src[j + 1];
            int s2 = s_src[j + 2], s3 = s_src[j + 3];
            float w0 = wf[(j + 0) * 4 + wid];
            float w1 = wf[(j + 1) * 4 + wid];
            float w2 = wf[(j + 2) * 4 + wid];
            float w3 = wf[(j + 3) * 4 + wid];
            float2 v0 = *reinterpret_cast<const float2*>(hp + (size_t)s0 * F1);
            float2 v1 = *reinterpret_cast<const float2*>(hp + (size_t)s1 * F1);
            float2 v2 = *reinterpret_cast<const float2*>(hp + (size_t)s2 * F1);
            float2 v3 = *reinterpret_cast<const float2*>(hp + (size_t)s3 * F1);
            a0 += w0 * v0.x; a1 += w0 * v0.y;
            a0 += w1 * v1.x; a1 += w1 * v1.y;
            a0 += w2 * v2.x; a1 += w2 * v2.y;
            a0 += w3 * v3.x; a1 += w3 * v3.y;
        }
        for (; j < cn; j++) {
            int s = s_src[j];
            float w = wf[j * 4 + wid];
            float2 hv = *reinterpret_cast<const float2*>(hp + (size_t)s * F1);
            a0 += w * hv.x;
            a1 += w * hv.y;
        }
        __syncthreads();
    }
#pragma unroll
    for (int off = 16; off >= 1; off >>= 1) {
        dpart.x += __shfl_xor_sync(0xffffffffu, dpart.x, off);
        dpart.y += __shfl_xor_sync(0xffffffffu, dpart.y, off);
        dpart.z += __shfl_xor_sync(0xffffffffu, dpart.z, off);
        dpart.w += __shfl_xor_sync(0xffffffffu, dpart.w, off);
    }
    if (lane == 0) s_red[wid] = dpart;
    __syncthreads();
    float4 dt = s_red[0];
    dt.x += s_red[1].x + s_red[2].x + s_red[3].x;
    dt.y += s_red[1].y + s_red[2].y + s_red[3].y;
    dt.z += s_red[1].z + s_red[2].z + s_red[3].z;
    dt.w += s_red[1].w + s_red[2].w + s_red[3].w;
    float den = ((const float*)&dt)[wid] + 1e-16f;
    float inv = 1.f / den;
    int c = tid * 2;
    float o0 = a0 * inv + bias[c];
    float o1 = a1 * inv + bias[c + 1];
    o0 = o0 > 0.f ? o0 : 0.f;
    o1 = o1 > 0.f ? o1 : 0.f;
    *reinterpret_cast<float2*>(out + (size_t)n * F1 + c) = make_float2(o0, o1);
}

__global__ __launch_bounds__(128) void gat_agg2(
    const float* __restrict__ h, const float* __restrict__ es, const float* __restrict__ ed,
    const float* __restrict__ bias, const float* __restrict__ gamma,
    const float* __restrict__ beta, float* __restrict__ out) {
    int n = blockIdx.x;
    int tid = threadIdx.x;
    int lane = tid & 31, wid = tid >> 5;
    int r0 = g_rowptr[n], r1 = g_rowptr[n + 1];
    int deg = r1 - r0;
    float4 edv = *reinterpret_cast<const float4*>(ed + n * 4);

    __shared__ float4 s_red[4];
    __shared__ int    s_src[CHUNK];
    __shared__ float4 s_w[CHUNK];
    __shared__ float  s_y[F2];
    __shared__ float  s_ln[4];

    const float* hp = h + tid * 4;

    float a0 = 0.f, a1 = 0.f, a2 = 0.f, a3 = 0.f;
    float4 dpart = make_float4(0.f, 0.f, 0.f, 0.f);
    for (int base = 0; base < deg; base += CHUNK) {
        int cn = deg - base; if (cn > CHUNK) cn = CHUNK;
        if (tid < cn) {
            int s = g_srcs[r0 + base + tid];
            float4 w = expleaky4(*reinterpret_cast<const float4*>(es + s * 4), edv);
            s_src[tid] = s;
            s_w[tid] = w;
            dpart.x += w.x; dpart.y += w.y; dpart.z += w.z; dpart.w += w.w;
        }
        __syncthreads();
        const float* wf = reinterpret_cast<const float*>(s_w);
        int j = 0;
        for (; j + 4 <= cn; j += 4) {
            int s0 = s_src[j + 0], s1 = s_src[j + 1];
            int s2 = s_src[j + 2], s3 = s_src[j + 3];
            float w0 = wf[(j + 0) * 4 + wid];
            float w1 = wf[(j + 1) * 4 + wid];
            float w2 = wf[(j + 2) * 4 + wid];
            float w3 = wf[(j + 3) * 4 + wid];
            float4 v0 = *reinterpret_cast<const float4*>(hp + (size_t)s0 * F2);
            float4 v1 = *reinterpret_cast<const float4*>(hp + (size_t)s1 * F2);
            float4 v2 = *reinterpret_cast<const float4*>(hp + (size_t)s2 * F2);
            float4 v3 = *reinterpret_cast<const float4*>(hp + (size_t)s3 * F2);
            a0 += w0 * v0.x; a1 += w0 * v0.y; a2 += w0 * v0.z; a3 += w0 * v0.w;
            a0 += w1 * v1.x; a1 += w1 * v1.y; a2 += w1 * v1.z; a3 += w1 * v1.w;
            a0 += w2 * v2.x; a1 += w2 * v2.y; a2 += w2 * v2.z; a3 += w2 * v2.w;
            a0 += w3 * v3.x; a1 += w3 * v3.y; a2 += w3 * v3.z; a3 += w3 * v3.w;
        }
        for (; j < cn; j++) {
            int s = s_src[j];
            float w = wf[j * 4 + wid];
            float4 hv = *reinterpret_cast<const float4*>(hp + (size_t)s * F2);
            a0 += w * hv.x;
            a1 += w * hv.y;
            a2 += w * hv.z;
            a3 += w * hv.w;
        }
        __syncthreads();
    }
#pragma unroll
    for (int off = 16; off >= 1; off >>= 1) {
        dpart.x += __shfl_xor_sync(0xffffffffu, dpart.x, off);
        dpart.y += __shfl_xor_sync(0xffffffffu, dpart.y, off);
        dpart.z += __shfl_xor_sync(0xffffffffu, dpart.z, off);
        dpart.w += __shfl_xor_sync(0xffffffffu, dpart.w, off);
    }
    if (lane == 0) s_red[wid] = dpart;
    __syncthreads();
    float4 dt = s_red[0];
    dt.x += s_red[1].x + s_red[2].x + s_red[3].x;
    dt.y += s_red[1].y + s_red[2].y + s_red[3].y;
    dt.z += s_red[1].z + s_red[2].z + s_red[3].z;
    dt.w += s_red[1].w + s_red[2].w + s_red[3].w;
    float inv = 1.f / (((const float*)&dt)[wid] + 1e-16f);
    int l = tid * 4;
    s_y[l + 0] = a0 * inv;
    s_y[l + 1] = a1 * inv;
    s_y[l + 2] = a2 * inv;
    s_y[l + 3] = a3 * inv;
    __syncthreads();

    int c = tid;
    float y = 0.25f * (s_y[c] + s_y[128 + c] + s_y[256 + c] + s_y[384 + c]) + bias[c];
    float t = y;
#pragma unroll
    for (int off = 16; off >= 1; off >>= 1) t += __shfl_xor_sync(0xffffffffu, t, off);
    if (lane == 0) s_ln[wid] = t;
    __syncthreads();
    float mu = (s_ln[0] + s_ln[1] + s_ln[2] + s_ln[3]) * (1.f / 128.f);
    float dv = y - mu;
    t = dv * dv;
#pragma unroll
    for (int off = 16; off >= 1; off >>= 1) t += __shfl_xor_sync(0xffffffffu, t, off);
    __syncthreads();
    if (lane == 0) s_ln[wid] = t;
    __syncthreads();
    float var = (s_ln[0] + s_ln[1] + s_ln[2] + s_ln[3]) * (1.f / 128.f);
    out[(size_t)n * 128 + c] = dv * rsqrtf(var + 1e-5f) * gamma[c] + beta[c];
}

// ---------------- launch ----------------
extern "C" void kernel_launch(void* const* d_in, const int* in_sizes, int n_in,
                              void* d_out, int out_size) {
    const float* x     = (const float*)d_in[0];
    const void*  ei    = d_in[1];
    const float* W1    = (const float*)d_in[2];
    const float* as1   = (const float*)d_in[3];
    const float* ad1   = (const float*)d_in[4];
    const float* b1    = (const float*)d_in[5];
    const float* W2    = (const float*)d_in[6];
    const float* as2   = (const float*)d_in[7];
    const float* ad2   = (const float*)d_in[8];
    const float* b2    = (const float*)d_in[9];
    const float* gamma = (const float*)d_in[10];
    const float* beta  = (const float*)d_in[11];
    float*       out   = (float*)d_out;

    float *p_h1, *p_hr, *p_h2, *p_es, *p_ed;
    cudaGetSymbolAddress((void**)&p_h1, g_h1);
    cudaGetSymbolAddress((void**)&p_hr, g_hr);
    cudaGetSymbolAddress((void**)&p_h2, g_h2);
    cudaGetSymbolAddress((void**)&p_es, g_es);
    cudaGetSymbolAddress((void**)&p_ed, g_ed);

    cudaFuncSetAttribute(gemm_db<64>,  cudaFuncAttributeMaxDynamicSharedMemorySize, GEMM_SMEM);
    cudaFuncSetAttribute(gemm_db<128>, cudaFuncAttributeMaxDynamicSharedMemorySize, GEMM_SMEM);

    const int TB = 256;
    int rows128 = (NN + 127) / 128;             // 391
    int edgeBlocks = (ETOT + TB - 1) / TB;      // 3321

    // ---- CSR build ----
    detect_idx_kernel<<<1, 32>>>((const int*)ei);
    zero_deg<<<(NN + TB - 1) / TB, TB>>>();
    hist_kernel<<<edgeBlocks, TB>>>(ei);
    scan_tiles<<<NT, 1024>>>();
    scan_parts<<<1, 64>>>();
    add_offsets<<<NT, 1024>>>();
    scatter_kernel<<<edgeBlocks, TB>>>(ei);

    // ---- layer 1 (scores fused into GEMM epilogue) ----
    gemm_db<64><<<dim3(F1 / 128, rows128), 256, GEMM_SMEM>>>(
        x, W1, p_h1, NN, 128, F1, as1, ad1, p_es, p_ed);
    gat_agg1<<<NN, 128>>>(p_h1, p_es, p_ed, b1, p_hr);

    // ---- layer 2 (scores fused into GEMM epilogue) ----
    gemm_db<128><<<dim3(F2 / 128, rows128), 256, GEMM_SMEM>>>(
        p_hr, W2, p_h2, NN, 256, F2, as2, ad2, p_es, p_ed);
    gat_agg2<<<NN, 128>>>(p_h2, p_es, p_ed, b2, gamma, beta, out);
}